// round 1
// baseline (speedup 1.0000x reference)
#include <cuda_runtime.h>
#include <math.h>

// Problem constants (fixed by setup_inputs)
#define BB 8
#define TT 600
#define CC 8
#define FF 257
#define NTAPS 5
#define NDELAY 3
#define KC 40           // NTAPS*CC
#define EPSV 1e-10f
#define NTHREADS 256
// valid frame count Tq = T - DELAY - TAPS + 1 = 593; u in [4, 597)

// Scratch: Y and enhanced in (B,F,C,T) complex layout
__device__ float2 g_Y[(size_t)BB*FF*CC*TT];
__device__ float2 g_E[(size_t)BB*FF*CC*TT];

struct WpeSmem {
    float2 Y[CC][TT];          // 38400 B
    float2 E[CC][TT];          // 38400 B
    float  invp[TT];           //  2400 B
    float2 R[KC][KC+1];        // 13120 B (padded row)
    float2 P[NTAPS][CC][CC];   //  2560 B  [k][e][d]
    float2 X[CC][KC];          //  2560 B  per-c solution
    float2 G[NTAPS][CC][CC];   //  2560 B  [p][d][e]
};                             // total 100000 B

__device__ __forceinline__ void cmac(float2& acc, float2 a, float2 b) {
    // acc += a * b
    acc.x += a.x*b.x - a.y*b.y;
    acc.y += a.x*b.y + a.y*b.x;
}

// ---------------------------------------------------------------------------
// Transpose in: (B,T,C,F) real+imag planes -> g_Y (B,F,C,T) float2
// ---------------------------------------------------------------------------
__global__ void k_transpose_in(const float* __restrict__ re,
                               const float* __restrict__ im) {
    __shared__ float2 tile[32][33];
    int bc = blockIdx.z;
    int b = bc / CC, c = bc % CC;
    int f0 = blockIdx.x * 32, t0 = blockIdx.y * 32;
    int tx = threadIdx.x, ty = threadIdx.y;
#pragma unroll
    for (int j = 0; j < 4; j++) {
        int t = t0 + ty + j*8, f = f0 + tx;
        if (t < TT && f < FF) {
            size_t idx = ((size_t)(b*TT + t)*CC + c)*FF + f;
            tile[ty + j*8][tx] = make_float2(re[idx], im[idx]);
        }
    }
    __syncthreads();
#pragma unroll
    for (int j = 0; j < 4; j++) {
        int f = f0 + ty + j*8, t = t0 + tx;
        if (t < TT && f < FF) {
            g_Y[((size_t)(b*FF + f)*CC + c)*TT + t] = tile[tx][ty + j*8];
        }
    }
}

// ---------------------------------------------------------------------------
// Transpose out: g_E (B,F,C,T) -> out real/imag planes (B,T,C,F), masked
// ---------------------------------------------------------------------------
__global__ void k_transpose_out(float* __restrict__ out,
                                const int* __restrict__ ilens) {
    __shared__ float2 tile[32][33];
    int bc = blockIdx.z;
    int b = bc / CC, c = bc % CC;
    int t0 = blockIdx.x * 32, f0 = blockIdx.y * 32;
    int tx = threadIdx.x, ty = threadIdx.y;
    int ilen = ilens[b];
    const size_t N = (size_t)BB*TT*CC*FF;
#pragma unroll
    for (int j = 0; j < 4; j++) {
        int f = f0 + ty + j*8, t = t0 + tx;
        if (t < TT && f < FF) {
            tile[ty + j*8][tx] = g_E[((size_t)(b*FF + f)*CC + c)*TT + t];
        }
    }
    __syncthreads();
#pragma unroll
    for (int j = 0; j < 4; j++) {
        int t = t0 + ty + j*8, f = f0 + tx;
        if (t < TT && f < FF) {
            float2 v = tile[tx][ty + j*8];
            if (t >= ilen) v = make_float2(0.f, 0.f);
            size_t idx = ((size_t)(b*TT + t)*CC + c)*FF + f;
            out[idx]     = v.x;
            out[N + idx] = v.y;
        }
    }
}

// ---------------------------------------------------------------------------
// Fused WPE: one CTA per (b,f). 2 iterations entirely in shared memory.
// ---------------------------------------------------------------------------
__global__ __launch_bounds__(NTHREADS, 2) void k_wpe() {
    extern __shared__ char smem_raw[];
    WpeSmem* s = (WpeSmem*)smem_raw;
    int bf = blockIdx.x;
    int tid = threadIdx.x;

    // Load Y (C,T) contiguously
    const float2* Yg = g_Y + (size_t)bf * CC * TT;
    float2* sYf = &s->Y[0][0];
    for (int i = tid; i < CC*TT; i += NTHREADS) sYf[i] = Yg[i];
    __syncthreads();

    for (int it = 0; it < 2; it++) {
        // ---- power -> invp (from Y on iter0, from enhanced on iter1) ----
        const float2 (*src)[TT] = (it == 0) ? s->Y : s->E;
        for (int t = tid; t < TT; t += NTHREADS) {
            float sum = 0.f;
#pragma unroll
            for (int c = 0; c < CC; c++) {
                float2 y = src[c][t];
                sum += y.x*y.x + y.y*y.y;
            }
            float p = sum * (1.0f / CC);
            s->invp[t] = 1.0f / fmaxf(p, EPSV);
        }
        // zero R and P
        {
            float2* rf = &s->R[0][0];
            for (int i = tid; i < KC*(KC+1); i += NTHREADS) rf[i] = make_float2(0.f, 0.f);
            float2* pf = &s->P[0][0][0];
            for (int i = tid; i < NTAPS*CC*CC; i += NTHREADS) pf[i] = make_float2(0.f, 0.f);
        }
        __syncthreads();

        // ---- R accumulation: 36 unordered channel pairs (d<=e) x 7 u-chunks ----
        // R[k*C+d][l*C+e] = sum_u conj(Y[d][u-k]) * invp[u+3] * Y[e][u-l], u in [4,597)
        if (tid < 252) {
            int pi = tid % 36, chunk = tid / 36;
            int e = 0;
            while ((e+1)*(e+2)/2 <= pi) e++;
            int d = pi - e*(e+1)/2;              // d <= e
            int u0 = 4 + chunk * 85;
            int u1 = min(597, u0 + 85);

            float2 acc[NTAPS][NTAPS];
#pragma unroll
            for (int k = 0; k < NTAPS; k++)
#pragma unroll
                for (int l = 0; l < NTAPS; l++) acc[k][l] = make_float2(0.f, 0.f);

            float2 wd[NTAPS], we[NTAPS];
#pragma unroll
            for (int k = 0; k < NTAPS-1; k++) {
                wd[k] = s->Y[d][u0-1-k];
                we[k] = s->Y[e][u0-1-k];
            }
            wd[NTAPS-1] = we[NTAPS-1] = make_float2(0.f, 0.f);

            for (int u = u0; u < u1; u++) {
#pragma unroll
                for (int k = NTAPS-1; k > 0; k--) { wd[k] = wd[k-1]; we[k] = we[k-1]; }
                wd[0] = s->Y[d][u];
                we[0] = s->Y[e][u];
                float w = s->invp[u+3];
#pragma unroll
                for (int k = 0; k < NTAPS; k++) {
                    float2 a = make_float2(w * wd[k].x, -w * wd[k].y);   // conj * w
#pragma unroll
                    for (int l = 0; l < NTAPS; l++) cmac(acc[k][l], a, we[l]);
                }
            }
#pragma unroll
            for (int k = 0; k < NTAPS; k++)
#pragma unroll
                for (int l = 0; l < NTAPS; l++) {
                    atomicAdd(&s->R[k*CC+d][l*CC+e].x, acc[k][l].x);
                    atomicAdd(&s->R[k*CC+d][l*CC+e].y, acc[k][l].y);
                }
        }
        __syncthreads();

        // ---- Hermitian mirror for d<e pairs ----
        for (int idx = tid; idx < 28*25; idx += NTHREADS) {
            int pi = idx / 25, kl = idx % 25;
            int e = 1;
            while (e*(e+1)/2 <= pi) e++;
            int d = pi - e*(e-1)/2;             // d < e
            int k = kl / 5, l = kl % 5;
            float2 v = s->R[l*CC+d][k*CC+e];
            s->R[k*CC+e][l*CC+d] = make_float2(v.x, -v.y);
        }

        // ---- P accumulation: 64 ordered pairs x 4 u-chunks ----
        // P[k][e][d] = sum_u conj(Y[d][u-k]) * invp[u+3] * Y[e][u+3]
        {
            int pi = tid % 64, chunk = tid / 64;
            int d = pi % CC, e = pi / CC;
            int u0 = 4 + chunk * 149;
            int u1 = min(597, u0 + 149);
            float2 accp[NTAPS];
#pragma unroll
            for (int k = 0; k < NTAPS; k++) accp[k] = make_float2(0.f, 0.f);
            for (int u = u0; u < u1; u++) {
                float w = s->invp[u+3];
                float2 ye = s->Y[e][u+3];
                float2 sv = make_float2(w * ye.x, w * ye.y);
#pragma unroll
                for (int k = 0; k < NTAPS; k++) {
                    float2 yd = s->Y[d][u-k];
                    // accp += conj(yd) * sv
                    accp[k].x += yd.x*sv.x + yd.y*sv.y;
                    accp[k].y += yd.x*sv.y - yd.y*sv.x;
                }
            }
#pragma unroll
            for (int k = 0; k < NTAPS; k++) {
                atomicAdd(&s->P[k][e][d].x, accp[k].x);
                atomicAdd(&s->P[k][e][d].y, accp[k].y);
            }
        }
        __syncthreads();

        // ---- regularize + in-place Cholesky of R (lower) ----
        if (tid < KC) s->R[tid][tid].x += EPSV;
        __syncthreads();
        for (int j = 0; j < KC; j++) {
            if (tid == 0) {
                float dv = sqrtf(fmaxf(s->R[j][j].x, 1e-30f));
                s->R[j][j] = make_float2(dv, 0.f);
            }
            __syncthreads();
            float dinv = 1.0f / s->R[j][j].x;
            for (int i = j + 1 + tid; i < KC; i += NTHREADS) {
                s->R[i][j].x *= dinv;
                s->R[i][j].y *= dinv;
            }
            __syncthreads();
            int m = KC - 1 - j;
            int tot = m * (m + 1) / 2;
            for (int idx = tid; idx < tot; idx += NTHREADS) {
                int lr = (int)(0.5f * (sqrtf(8.f * (float)idx + 1.f) - 1.f));
                while ((lr+1)*(lr+2)/2 <= idx) lr++;
                while (lr*(lr+1)/2 > idx) lr--;
                int lc = idx - lr*(lr+1)/2;
                int i = j + 1 + lr, l = j + 1 + lc;
                float2 Lij = s->R[i][j], Llj = s->R[l][j];
                // R[i][l] -= Lij * conj(Llj)
                s->R[i][l].x -= Lij.x*Llj.x + Lij.y*Llj.y;
                s->R[i][l].y -= Lij.y*Llj.x - Lij.x*Llj.y;
            }
            __syncthreads();
        }

        // ---- triangular solves: warp c solves R x = vec_c ----
        {
            int warp = tid >> 5, lane = tid & 31;   // warp = output channel c
            for (int i = lane; i < KC; i += 32) {
                int k = i >> 3, d = i & 7;
                s->X[warp][i] = s->P[k][warp][d];
            }
            __syncwarp();
            // forward: L y = v
            for (int j = 0; j < KC; j++) {
                if (lane == 0) {
                    float dinv = 1.0f / s->R[j][j].x;
                    s->X[warp][j].x *= dinv;
                    s->X[warp][j].y *= dinv;
                }
                __syncwarp();
                float2 yj = s->X[warp][j];
                for (int i = j + 1 + lane; i < KC; i += 32) {
                    float2 L = s->R[i][j];
                    s->X[warp][i].x -= L.x*yj.x - L.y*yj.y;
                    s->X[warp][i].y -= L.x*yj.y + L.y*yj.x;
                }
                __syncwarp();
            }
            // backward: L^H x = y
            for (int j = KC - 1; j >= 0; j--) {
                if (lane == 0) {
                    float dinv = 1.0f / s->R[j][j].x;
                    s->X[warp][j].x *= dinv;
                    s->X[warp][j].y *= dinv;
                }
                __syncwarp();
                float2 xj = s->X[warp][j];
                for (int i = lane; i < j; i += 32) {
                    float2 L = s->R[j][i];
                    // x[i] -= conj(L) * xj
                    s->X[warp][i].x -= L.x*xj.x + L.y*xj.y;
                    s->X[warp][i].y -= L.x*xj.y - L.y*xj.x;
                }
                __syncwarp();
            }
        }
        __syncthreads();

        // ---- G_conj[p][d][e] = X[e][p*C+d] ----
        for (int idx = tid; idx < NTAPS*CC*CC; idx += NTHREADS) {
            int p = idx / (CC*CC), r = idx % (CC*CC);
            int d = r / CC, e = r % CC;
            s->G[p][d][e] = s->X[e][p*CC + d];
        }
        __syncthreads();

        // ---- enhanced = Y - sum_{p,d} G[p][d][e] * Y[d][t-3-p] ----
        {
            int warp = tid >> 5, lane = tid & 31;
            int e = warp;
            for (int t = lane; t < TT; t += 32) {
                float2 acc = s->Y[e][t];
#pragma unroll
                for (int p = 0; p < NTAPS; p++) {
                    int tp = t - NDELAY - p;
                    if (tp >= 0) {
#pragma unroll
                        for (int d = 0; d < CC; d++) {
                            float2 g = s->G[p][d][e];
                            float2 y = s->Y[d][tp];
                            acc.x -= g.x*y.x - g.y*y.y;
                            acc.y -= g.x*y.y + g.y*y.x;
                        }
                    }
                }
                s->E[e][t] = acc;
            }
        }
        __syncthreads();
    } // iterations

    // write enhanced coalesced
    float2* Eg = g_E + (size_t)bf * CC * TT;
    float2* sEf = &s->E[0][0];
    for (int i = tid; i < CC*TT; i += NTHREADS) Eg[i] = sEf[i];
}

// ---------------------------------------------------------------------------
extern "C" void kernel_launch(void* const* d_in, const int* in_sizes, int n_in,
                              void* d_out, int out_size) {
    const float* re    = (const float*)d_in[0];
    const float* im    = (const float*)d_in[1];
    const int*   ilens = (const int*)d_in[2];
    float* out = (float*)d_out;

    cudaFuncSetAttribute(k_wpe, cudaFuncAttributeMaxDynamicSharedMemorySize,
                         (int)sizeof(WpeSmem));

    dim3 blk(32, 8);
    k_transpose_in<<<dim3((FF+31)/32, (TT+31)/32, BB*CC), blk>>>(re, im);
    k_wpe<<<BB*FF, NTHREADS, sizeof(WpeSmem)>>>();
    k_transpose_out<<<dim3((TT+31)/32, (FF+31)/32, BB*CC), blk>>>(out, ilens);
}